// round 15
// baseline (speedup 1.0000x reference)
#include <cuda_runtime.h>
#include <cuda_bf16.h>

#define N_SEQ 2048
#define DIM   1024
#define NB    4
#define NH    16
#define DH    64
#define MTOT (NB * N_SEQ)   // 8192

// ---------------------------------------------------------------------------
// Scratch (no allocs allowed -> __device__ globals)
// ---------------------------------------------------------------------------
__device__ __nv_bfloat16 g_ahi[(size_t)MTOT * DIM];     // x-split
__device__ __nv_bfloat16 g_alo[(size_t)MTOT * DIM];
__device__ __nv_bfloat16 g_wqh[(size_t)DIM * DIM];      // Wq^T hi  [n][k]
__device__ __nv_bfloat16 g_wql[(size_t)DIM * DIM];
__device__ __nv_bfloat16 g_wkh[(size_t)DH * DIM];       // Wkv^T hi [64][1024]
__device__ __nv_bfloat16 g_wkl[(size_t)DH * DIM];
__device__ __nv_bfloat16 g_qhi[(size_t)NB * NH * N_SEQ * DH];  // [b,h,n,d]
__device__ __nv_bfloat16 g_qlo[(size_t)NB * NH * N_SEQ * DH];
__device__ __nv_bfloat16 g_kh[(size_t)NB * N_SEQ * DH]; // token-indexed [b][n][d]
__device__ __nv_bfloat16 g_kl[(size_t)NB * N_SEQ * DH];
__device__ __nv_bfloat16 g_vth[(size_t)NB * DH * N_SEQ];// transposed [b][d][n]
__device__ __nv_bfloat16 g_vtl[(size_t)NB * DH * N_SEQ];
// int8 dual-level operands for the out-projection
__device__ signed char g_a8h[(size_t)MTOT * DIM];       // att quantized hi
__device__ signed char g_a8l[(size_t)MTOT * DIM];       // att residual
__device__ signed char g_w8h[(size_t)DIM * DIM];        // Wout^T quantized hi
__device__ signed char g_w8l[(size_t)DIM * DIM];

// quantization scales: |att| <= ~4.9 (convex combo of kv~N(0,1)), |Wout|<=0.25
#define QS_ATT (127.f / 7.f)
#define QS_W   (127.f / 0.25f)
#define OUT_SCL ((7.f / 127.f) * (0.25f / 127.f))

// ---------------------------------------------------------------------------
// helpers
// ---------------------------------------------------------------------------
__device__ __forceinline__ unsigned smem_u32(const void* p) {
    unsigned a;
    asm("{ .reg .u64 t; cvta.to.shared.u64 t, %1; cvt.u32.u64 %0, t; }"
        : "=r"(a) : "l"(p));
    return a;
}
__device__ __forceinline__ void cp16(unsigned dst, const void* src) {
    asm volatile("cp.async.cg.shared.global [%0], [%1], 16;"
                 :: "r"(dst), "l"(src) : "memory");
}
__device__ __forceinline__ void cp_commit() {
    asm volatile("cp.async.commit_group;" ::: "memory");
}
__device__ __forceinline__ void mma_bf16(float* acc, unsigned a0, unsigned a1,
                                         unsigned a2, unsigned a3,
                                         unsigned b0, unsigned b1) {
    asm volatile("mma.sync.aligned.m16n8k16.row.col.f32.bf16.bf16.f32 "
                 "{%0,%1,%2,%3}, {%4,%5,%6,%7}, {%8,%9}, {%0,%1,%2,%3};"
                 : "+f"(acc[0]), "+f"(acc[1]), "+f"(acc[2]), "+f"(acc[3])
                 : "r"(a0), "r"(a1), "r"(a2), "r"(a3), "r"(b0), "r"(b1));
}
__device__ __forceinline__ void mma_s8(int* acc, unsigned a0, unsigned a1,
                                       unsigned a2, unsigned a3,
                                       unsigned b0, unsigned b1) {
    asm volatile("mma.sync.aligned.m16n8k32.row.col.s32.s8.s8.s32 "
                 "{%0,%1,%2,%3}, {%4,%5,%6,%7}, {%8,%9}, {%0,%1,%2,%3};"
                 : "+r"(acc[0]), "+r"(acc[1]), "+r"(acc[2]), "+r"(acc[3])
                 : "r"(a0), "r"(a1), "r"(a2), "r"(a3), "r"(b0), "r"(b1));
}
__device__ __forceinline__ unsigned lds32(const __nv_bfloat16* p) {
    return *(const unsigned*)p;
}
__device__ __forceinline__ void split2(float x, float y, unsigned& hi, unsigned& lo) {
    __nv_bfloat16 hx = __float2bfloat16(x), hy = __float2bfloat16(y);
    __nv_bfloat162 h2 = __halves2bfloat162(hx, hy);
    hi = *(unsigned*)&h2;
    __nv_bfloat16 lx = __float2bfloat16(x - __bfloat162float(hx));
    __nv_bfloat16 ly = __float2bfloat16(y - __bfloat162float(hy));
    __nv_bfloat162 l2 = __halves2bfloat162(lx, ly);
    lo = *(unsigned*)&l2;
}
__device__ __forceinline__ void split1(float x, __nv_bfloat16& h, __nv_bfloat16& l) {
    h = __float2bfloat16(x);
    l = __float2bfloat16(x - __bfloat162float(h));
}
// dual-level int8 quantization: x*qs ~= h + l/256, h,l int8
__device__ __forceinline__ void quant8(float x, float qs, int& h, int& l) {
    float u = x * qs;
    h = __float2int_rn(u);
    h = max(-127, min(127, h));
    float r = u - (float)h;
    l = __float2int_rn(r * 256.f);
    l = max(-128, min(127, l));
}

// ---------------------------------------------------------------------------
// split: fp32 -> bf16 hi + bf16 residual (linear)
// ---------------------------------------------------------------------------
__global__ void split_kernel(const float* __restrict__ s,
                             __nv_bfloat16* __restrict__ hi,
                             __nv_bfloat16* __restrict__ lo, int n) {
    int i = (blockIdx.x * blockDim.x + threadIdx.x) * 4;
    if (i >= n) return;
    float4 v = *(const float4*)(s + i);
    unsigned h0, l0, h1, l1;
    split2(v.x, v.y, h0, l0);
    split2(v.z, v.w, h1, l1);
    *(unsigned*)(hi + i)     = h0;
    *(unsigned*)(hi + i + 2) = h1;
    *(unsigned*)(lo + i)     = l0;
    *(unsigned*)(lo + i + 2) = l1;
}

// ---------------------------------------------------------------------------
// transpose+split weights: W[k][ncols] fp32 -> Wt hi/lo [ncols][1024] bf16
// ---------------------------------------------------------------------------
__global__ void tsplit_kernel(const float* __restrict__ W, int ncols,
                              __nv_bfloat16* __restrict__ hi,
                              __nv_bfloat16* __restrict__ lo) {
    __shared__ float t[32][33];
    int n0 = blockIdx.x * 32, k0 = blockIdx.y * 32;
    int tx = threadIdx.x, ty = threadIdx.y;
    #pragma unroll
    for (int j = 0; j < 32; j += 8)
        t[ty + j][tx] = W[(size_t)(k0 + ty + j) * ncols + n0 + tx];
    __syncthreads();
    #pragma unroll
    for (int j = 0; j < 32; j += 8) {
        float v = t[tx][ty + j];
        __nv_bfloat16 h, l;
        split1(v, h, l);
        size_t o = (size_t)(n0 + ty + j) * DIM + k0 + tx;
        hi[o] = h;
        lo[o] = l;
    }
}

// ---------------------------------------------------------------------------
// transpose+quantize Wout: W[k][1024] fp32 -> [n][k] int8 dual-level
// ---------------------------------------------------------------------------
__global__ void tquant_kernel(const float* __restrict__ W,
                              signed char* __restrict__ hi,
                              signed char* __restrict__ lo) {
    __shared__ float t[32][33];
    int n0 = blockIdx.x * 32, k0 = blockIdx.y * 32;
    int tx = threadIdx.x, ty = threadIdx.y;
    #pragma unroll
    for (int j = 0; j < 32; j += 8)
        t[ty + j][tx] = W[(size_t)(k0 + ty + j) * DIM + n0 + tx];
    __syncthreads();
    #pragma unroll
    for (int j = 0; j < 32; j += 8) {
        float v = t[tx][ty + j];
        int h, l;
        quant8(v, QS_W, h, l);
        size_t o = (size_t)(n0 + ty + j) * DIM + k0 + tx;
        hi[o] = (signed char)h;
        lo[o] = (signed char)l;
    }
}

// ---------------------------------------------------------------------------
// mma.sync split-bf16 GEMM (Q projection): C = A @ Bt^T, 3-term split.
// ---------------------------------------------------------------------------
#define GLDK 40
__global__ __launch_bounds__(256)
void gemm_mma_kernel(const __nv_bfloat16* __restrict__ Ahi,
                     const __nv_bfloat16* __restrict__ Alo,
                     const __nv_bfloat16* __restrict__ Bhi,
                     const __nv_bfloat16* __restrict__ Blo,
                     float* __restrict__ C,
                     __nv_bfloat16* __restrict__ Chi,
                     __nv_bfloat16* __restrict__ Clo, int mode) {
    __shared__ __align__(16) __nv_bfloat16 sA[2][128 * GLDK];
    __shared__ __align__(16) __nv_bfloat16 sB[2][128 * GLDK];

    const int tid = threadIdx.x;
    const int lane = tid & 31;
    const int wid = tid >> 5;
    const int warpM = wid & 1;
    const int warpN = wid >> 1;
    const int g = lane >> 2, tig = lane & 3;
    const int m0 = blockIdx.y * 128;
    const int n0 = blockIdx.x * 128;

    const unsigned sa0 = smem_u32(&sA[0][0]);
    const unsigned sb0 = smem_u32(&sB[0][0]);

    float acc[4][4][4];
    #pragma unroll
    for (int i = 0; i < 4; i++)
        #pragma unroll
        for (int j = 0; j < 4; j++)
            #pragma unroll
            for (int e = 0; e < 4; e++) acc[i][j][e] = 0.f;

    const __nv_bfloat16* Aseg[3] = {Ahi, Ahi, Alo};
    const __nv_bfloat16* Bseg[3] = {Bhi, Blo, Bhi};

    const int lrow = tid >> 1;
    const int ljb  = (tid & 1) * 2;

    auto load_chunk = [&](int c, int st) {
        const int seg = c >> 5;
        const int k0  = (c & 31) * 32;
        const __nv_bfloat16* A = Aseg[seg];
        const __nv_bfloat16* B = Bseg[seg];
        #pragma unroll
        for (int i = 0; i < 2; i++) {
            int j = ljb + i;
            cp16(sa0 + (st * 128 * GLDK + lrow * GLDK + j * 8) * 2,
                 A + (size_t)(m0 + lrow) * DIM + k0 + j * 8);
            cp16(sb0 + (st * 128 * GLDK + lrow * GLDK + j * 8) * 2,
                 B + (size_t)(n0 + lrow) * DIM + k0 + j * 8);
        }
        cp_commit();
    };

    load_chunk(0, 0);

    #pragma unroll 1
    for (int c = 0; c < 96; c++) {
        const int st = c & 1;
        if (c + 1 < 96) {
            load_chunk(c + 1, st ^ 1);
            asm volatile("cp.async.wait_group 1;" ::: "memory");
        } else {
            asm volatile("cp.async.wait_group 0;" ::: "memory");
        }
        __syncthreads();

        const __nv_bfloat16* pa = &sA[st][0];
        const __nv_bfloat16* pb = &sB[st][0];
        #pragma unroll
        for (int ks = 0; ks < 2; ks++) {
            unsigned a[4][4];
            #pragma unroll
            for (int mt = 0; mt < 4; mt++) {
                int row = warpM * 64 + mt * 16 + g;
                const __nv_bfloat16* p = pa + row * GLDK + ks * 16 + tig * 2;
                a[mt][0] = lds32(p);
                a[mt][1] = lds32(p + 8 * GLDK);
                a[mt][2] = lds32(p + 8);
                a[mt][3] = lds32(p + 8 * GLDK + 8);
            }
            #pragma unroll
            for (int nt = 0; nt < 4; nt++) {
                int col = warpN * 32 + nt * 8 + g;
                const __nv_bfloat16* p = pb + col * GLDK + ks * 16 + tig * 2;
                unsigned b0 = lds32(p), b1 = lds32(p + 8);
                #pragma unroll
                for (int mt = 0; mt < 4; mt++)
                    mma_bf16(acc[mt][nt], a[mt][0], a[mt][1], a[mt][2], a[mt][3], b0, b1);
            }
        }
        __syncthreads();
    }

    #pragma unroll
    for (int mt = 0; mt < 4; mt++) {
        #pragma unroll
        for (int nt = 0; nt < 4; nt++) {
            int gr = m0 + warpM * 64 + mt * 16 + g;
            int gc = n0 + warpN * 32 + nt * 8 + tig * 2;
            #pragma unroll
            for (int hh = 0; hh < 2; hh++) {
                int r = gr + hh * 8;
                if (mode == 1) {
                    float vx = acc[mt][nt][hh * 2] * 0.125f;
                    float vy = acc[mt][nt][hh * 2 + 1] * 0.125f;
                    unsigned h, l;
                    split2(vx, vy, h, l);
                    int b = r >> 11, ii = r & 2047, hd = gc >> 6;
                    size_t off = (((size_t)(b * NH + hd) * N_SEQ + ii)) * DH + (gc & 63);
                    *(unsigned*)(Chi + off) = h;
                    *(unsigned*)(Clo + off) = l;
                } else {
                    float2 v = make_float2(acc[mt][nt][hh * 2], acc[mt][nt][hh * 2 + 1]);
                    *(float2*)(C + (size_t)r * DIM + gc) = v;
                }
            }
        }
    }
}

// ---------------------------------------------------------------------------
// int8 dual-level GEMM (out projection): out = att @ Wout^T.
// 4 exact segments: AhBh (1) + AhBl (1/256) + AlBh (1/256) + AlBl (1/65536),
// int32-exact per segment, folded into fp32 at segment boundaries.
// K chunks of 64 int8, 64 chunks (4 segments x 16), double-buffered.
// ---------------------------------------------------------------------------
#define IL8 80
__global__ __launch_bounds__(256)
void gemm_i8_kernel(const signed char* __restrict__ Ah,
                    const signed char* __restrict__ Al,
                    const signed char* __restrict__ Bh,
                    const signed char* __restrict__ Bl,
                    float* __restrict__ C) {
    __shared__ __align__(16) signed char sA[2][128 * IL8];
    __shared__ __align__(16) signed char sB[2][128 * IL8];

    const int tid = threadIdx.x;
    const int lane = tid & 31;
    const int wid = tid >> 5;
    const int warpM = wid & 1;
    const int warpN = wid >> 1;
    const int g = lane >> 2, tig = lane & 3;
    const int m0 = blockIdx.y * 128;
    const int n0 = blockIdx.x * 128;

    const unsigned sa0 = smem_u32(&sA[0][0]);
    const unsigned sb0 = smem_u32(&sB[0][0]);

    int acc[4][4][4];
    float facc[4][4][4];
    #pragma unroll
    for (int i = 0; i < 4; i++)
        #pragma unroll
        for (int j = 0; j < 4; j++)
            #pragma unroll
            for (int e = 0; e < 4; e++) { acc[i][j][e] = 0; facc[i][j][e] = 0.f; }

    const signed char* Aseg[4] = {Ah, Ah, Al, Al};
    const signed char* Bseg[4] = {Bh, Bl, Bh, Bl};
    const float segw[4] = {1.f, 1.f / 256.f, 1.f / 256.f, 1.f / 65536.f};

    const int lrow = tid >> 1;
    const int ljb  = (tid & 1) * 2;

    auto load_chunk = [&](int c, int st) {
        const int seg = c >> 4;
        const int k0  = (c & 15) * 64;
        const signed char* A = Aseg[seg];
        const signed char* B = Bseg[seg];
        #pragma unroll
        for (int i = 0; i < 2; i++) {
            int j = ljb + i;                 // 0..3, 16 bytes each
            cp16(sa0 + st * 128 * IL8 + lrow * IL8 + j * 16,
                 A + (size_t)(m0 + lrow) * DIM + k0 + j * 16);
            cp16(sb0 + st * 128 * IL8 + lrow * IL8 + j * 16,
                 B + (size_t)(n0 + lrow) * DIM + k0 + j * 16);
        }
        cp_commit();
    };

    load_chunk(0, 0);

    #pragma unroll 1
    for (int c = 0; c < 64; c++) {
        const int st = c & 1;
        if (c + 1 < 64) {
            load_chunk(c + 1, st ^ 1);
            asm volatile("cp.async.wait_group 1;" ::: "memory");
        } else {
            asm volatile("cp.async.wait_group 0;" ::: "memory");
        }
        __syncthreads();

        const signed char* pa = &sA[st][0];
        const signed char* pb = &sB[st][0];
        #pragma unroll
        for (int ks = 0; ks < 2; ks++) {
            unsigned a[4][4];
            #pragma unroll
            for (int mt = 0; mt < 4; mt++) {
                const signed char* p = pa + (warpM * 64 + mt * 16 + g) * IL8 + ks * 32 + tig * 4;
                a[mt][0] = *(const unsigned*)p;
                a[mt][1] = *(const unsigned*)(p + 8 * IL8);
                a[mt][2] = *(const unsigned*)(p + 16);
                a[mt][3] = *(const unsigned*)(p + 8 * IL8 + 16);
            }
            #pragma unroll
            for (int nt = 0; nt < 4; nt++) {
                const signed char* p = pb + (warpN * 32 + nt * 8 + g) * IL8 + ks * 32 + tig * 4;
                unsigned b0 = *(const unsigned*)p, b1 = *(const unsigned*)(p + 16);
                #pragma unroll
                for (int mt = 0; mt < 4; mt++)
                    mma_s8(acc[mt][nt], a[mt][0], a[mt][1], a[mt][2], a[mt][3], b0, b1);
            }
        }
        __syncthreads();

        if ((c & 15) == 15) {           // segment boundary: fold exact int32 sum
            const float w = segw[c >> 4];
            #pragma unroll
            for (int i = 0; i < 4; i++)
                #pragma unroll
                for (int j = 0; j < 4; j++)
                    #pragma unroll
                    for (int e = 0; e < 4; e++) {
                        facc[i][j][e] += w * (float)acc[i][j][e];
                        acc[i][j][e] = 0;
                    }
        }
    }

    #pragma unroll
    for (int mt = 0; mt < 4; mt++) {
        #pragma unroll
        for (int nt = 0; nt < 4; nt++) {
            int gr = m0 + warpM * 64 + mt * 16 + g;
            int gc = n0 + warpN * 32 + nt * 8 + tig * 2;
            #pragma unroll
            for (int hh = 0; hh < 2; hh++) {
                int r = gr + hh * 8;
                float vx = facc[mt][nt][hh * 2] * OUT_SCL;
                float vy = facc[mt][nt][hh * 2 + 1] * OUT_SCL;
                *(float2*)(C + (size_t)r * DIM + gc) = make_float2(vx, vy);
            }
        }
    }
}

// ---------------------------------------------------------------------------
// KV projection on mma.sync split: kv = x @ Wkv, tile 128x64, K=3x1024.
// ---------------------------------------------------------------------------
__global__ __launch_bounds__(256)
void kvgemm_mma_kernel(const __nv_bfloat16* __restrict__ Ahi,
                       const __nv_bfloat16* __restrict__ Alo,
                       const __nv_bfloat16* __restrict__ Bhi,
                       const __nv_bfloat16* __restrict__ Blo,
                       __nv_bfloat16* __restrict__ kh,
                       __nv_bfloat16* __restrict__ kl,
                       __nv_bfloat16* __restrict__ vth,
                       __nv_bfloat16* __restrict__ vtl) {
    __shared__ __align__(16) __nv_bfloat16 sA[2][128 * GLDK];
    __shared__ __align__(16) __nv_bfloat16 sB[2][64 * GLDK];

    const int tid = threadIdx.x;
    const int lane = tid & 31;
    const int w = tid >> 5;
    const int g = lane >> 2, tig = lane & 3;
    const int m0 = blockIdx.x * 128;

    const unsigned sa0 = smem_u32(&sA[0][0]);
    const unsigned sb0 = smem_u32(&sB[0][0]);

    float acc[8][4];
    #pragma unroll
    for (int i = 0; i < 8; i++)
        #pragma unroll
        for (int e = 0; e < 4; e++) acc[i][e] = 0.f;

    const __nv_bfloat16* Aseg[3] = {Ahi, Ahi, Alo};
    const __nv_bfloat16* Bseg[3] = {Bhi, Blo, Bhi};

    auto load_chunk = [&](int c, int st) {
        const int seg = c >> 5;
        const int k0  = (c & 31) * 32;
        const __nv_bfloat16* A = Aseg[seg];
        const __nv_bfloat16* B = Bseg[seg];
        {
            const int row = tid >> 1;
            const int jb  = (tid & 1) * 2;
            #pragma unroll
            for (int i = 0; i < 2; i++) {
                int j = jb + i;
                cp16(sa0 + (st * 128 * GLDK + row * GLDK + j * 8) * 2,
                     A + (size_t)(m0 + row) * DIM + k0 + j * 8);
            }
        }
        {
            const int row = tid >> 2;
            const int j   = tid & 3;
            cp16(sb0 + (st * 64 * GLDK + row * GLDK + j * 8) * 2,
                 B + (size_t)row * DIM + k0 + j * 8);
        }
        cp_commit();
    };

    load_chunk(0, 0);

    #pragma unroll 1
    for (int c = 0; c < 96; c++) {
        const int st = c & 1;
        if (c + 1 < 96) {
            load_chunk(c + 1, st ^ 1);
            asm volatile("cp.async.wait_group 1;" ::: "memory");
        } else {
            asm volatile("cp.async.wait_group 0;" ::: "memory");
        }
        __syncthreads();

        const __nv_bfloat16* pa = &sA[st][0];
        const __nv_bfloat16* pb = &sB[st][0];
        #pragma unroll
        for (int ks = 0; ks < 2; ks++) {
            unsigned a[4];
            {
                int row = w * 16 + g;
                const __nv_bfloat16* p = pa + row * GLDK + ks * 16 + tig * 2;
                a[0] = lds32(p);
                a[1] = lds32(p + 8 * GLDK);
                a[2] = lds32(p + 8);
                a[3] = lds32(p + 8 * GLDK + 8);
            }
            #pragma unroll
            for (int nt = 0; nt < 8; nt++) {
                int col = nt * 8 + g;
                const __nv_bfloat16* p = pb + col * GLDK + ks * 16 + tig * 2;
                unsigned b0 = lds32(p), b1 = lds32(p + 8);
                mma_bf16(acc[nt], a[0], a[1], a[2], a[3], b0, b1);
            }
        }
        __syncthreads();
    }

    #pragma unroll
    for (int nt = 0; nt < 8; nt++) {
        #pragma unroll
        for (int hh = 0; hh < 2; hh++) {
            int gr = m0 + w * 16 + hh * 8 + g;
            int b = gr >> 11, ii = gr & 2047;
            int cc = nt * 8 + tig * 2;
            float vx = acc[nt][hh * 2], vy = acc[nt][hh * 2 + 1];
            unsigned h, l;
            split2(vx, vy, h, l);
            size_t ko = ((size_t)b * N_SEQ + ii) * DH + cc;
            *(unsigned*)(kh + ko) = h;
            *(unsigned*)(kl + ko) = l;
            __nv_bfloat16 h0, l0, h1, l1;
            split1(vx, h0, l0);
            split1(vy, h1, l1);
            size_t vo = ((size_t)b * DH + cc) * N_SEQ + ii;
            vth[vo] = h0; vtl[vo] = l0;
            vth[vo + N_SEQ] = h1; vtl[vo + N_SEQ] = l1;
        }
    }
}

// ---------------------------------------------------------------------------
// Flash attention on mma.sync, split-bf16 (3-term), double-buffered K/V,
// no-max softmax. Output quantized directly to int8 dual-level (out-proj A).
// ---------------------------------------------------------------------------
#define ALDK 72
#define QH0  0
#define QL0  (128 * ALDK)
#define KVB  (2 * 128 * ALDK)
#define KVST (4 * 64 * ALDK)
#define KH_(s) (KVB + (s) * KVST)
#define KL_(s) (KH_(s) + 64 * ALDK)
#define VH_(s) (KH_(s) + 2 * 64 * ALDK)
#define VL_(s) (KH_(s) + 3 * 64 * ALDK)
#define ATT_SMEM ((KVB + 2 * KVST) * 2)   // 110592 bytes

__global__ __launch_bounds__(256)
void attn_mma_kernel(const __nv_bfloat16* __restrict__ qhi,
                     const __nv_bfloat16* __restrict__ qlo,
                     const __nv_bfloat16* __restrict__ kh,
                     const __nv_bfloat16* __restrict__ kl,
                     const __nv_bfloat16* __restrict__ vth,
                     const __nv_bfloat16* __restrict__ vtl,
                     const float* __restrict__ nullkv,
                     signed char* __restrict__ a8h,
                     signed char* __restrict__ a8l) {
    extern __shared__ __align__(16) __nv_bfloat16 sm[];
    const unsigned sb = smem_u32(sm);

    const int tid = threadIdx.x;
    const int w = tid >> 5;
    const int lane = tid & 31;
    const int g = lane >> 2, tig = lane & 3;
    const int qb = 15 - blockIdx.x;
    const int bh = blockIdx.y;
    const int b = bh >> 4, head = bh & 15;
    const int qi0 = qb * 128;
    const int ntiles = 2 * qb + 2;

    auto load_kv = [&](int t, int st) {
        const int rr = tid >> 2, q = tid & 3;
        size_t ko = ((size_t)b * N_SEQ + t * 64 + rr) * DH;
        size_t vo = ((size_t)b * DH + rr) * N_SEQ + t * 64;
        #pragma unroll
        for (int i = 0; i < 2; i++) {
            int j = q * 2 + i;
            cp16(sb + (KH_(st) + rr * ALDK + j * 8) * 2, kh + ko + j * 8);
            cp16(sb + (KL_(st) + rr * ALDK + j * 8) * 2, kl + ko + j * 8);
            cp16(sb + (VH_(st) + rr * ALDK + j * 8) * 2, vth + vo + j * 8);
            cp16(sb + (VL_(st) + rr * ALDK + j * 8) * 2, vtl + vo + j * 8);
        }
        cp_commit();
    };

    {
        const int row = tid >> 1;
        const int half = tid & 1;
        size_t qo = ((size_t)bh * N_SEQ + qi0 + row) * DH + half * 32;
        #pragma unroll
        for (int j = 0; j < 4; j++) {
            cp16(sb + (QH0 + row * ALDK + half * 32 + j * 8) * 2, qhi + qo + j * 8);
            cp16(sb + (QL0 + row * ALDK + half * 32 + j * 8) * 2, qlo + qo + j * 8);
        }
    }
    load_kv(0, 0);

    float l_[2], O[8][4];

    #pragma unroll 1
    for (int t = 0; t < ntiles; t++) {
        const int st = t & 1;
        if (t) __syncthreads();
        if (t + 1 < ntiles) {
            load_kv(t + 1, st ^ 1);
            asm volatile("cp.async.wait_group 1;" ::: "memory");
        } else {
            asm volatile("cp.async.wait_group 0;" ::: "memory");
        }
        __syncthreads();

        if (t == 0) {
            float nk[16];
            #pragma unroll
            for (int d = 0; d < 16; d++) nk[d] = nullkv[tig * 16 + d];
            float e0s[2];
            #pragma unroll
            for (int hh = 0; hh < 2; hh++) {
                int row = w * 16 + hh * 8 + g;
                const __nv_bfloat16* ph = sm + QH0 + row * ALDK + tig * 16;
                const __nv_bfloat16* pl = sm + QL0 + row * ALDK + tig * 16;
                float s = 0.f;
                #pragma unroll
                for (int d = 0; d < 16; d++)
                    s = fmaf(__bfloat162float(ph[d]) + __bfloat162float(pl[d]),
                             nk[d], s);
                s += __shfl_xor_sync(0xffffffffu, s, 1);
                s += __shfl_xor_sync(0xffffffffu, s, 2);
                e0s[hh] = __expf(s);
                l_[hh] = (tig == 0) ? e0s[hh] : 0.f;
            }
            #pragma unroll
            for (int nt = 0; nt < 8; nt++) {
                float v0 = nullkv[nt * 8 + tig * 2];
                float v1 = nullkv[nt * 8 + tig * 2 + 1];
                O[nt][0] = v0 * e0s[0]; O[nt][1] = v1 * e0s[0];
                O[nt][2] = v0 * e0s[1]; O[nt][3] = v1 * e0s[1];
            }
        }

        float S[8][4];
        #pragma unroll
        for (int nt = 0; nt < 8; nt++)
            #pragma unroll
            for (int e = 0; e < 4; e++) S[nt][e] = 0.f;

        #pragma unroll
        for (int ks = 0; ks < 4; ks++) {
            unsigned ah[4], al[4];
            {
                int row = w * 16 + g;
                const __nv_bfloat16* ph = sm + QH0 + row * ALDK + ks * 16 + tig * 2;
                const __nv_bfloat16* pl = sm + QL0 + row * ALDK + ks * 16 + tig * 2;
                ah[0] = lds32(ph);            ah[1] = lds32(ph + 8 * ALDK);
                ah[2] = lds32(ph + 8);        ah[3] = lds32(ph + 8 * ALDK + 8);
                al[0] = lds32(pl);            al[1] = lds32(pl + 8 * ALDK);
                al[2] = lds32(pl + 8);        al[3] = lds32(pl + 8 * ALDK + 8);
            }
            #pragma unroll
            for (int nt = 0; nt < 8; nt++) {
                int col = nt * 8 + g;
                const __nv_bfloat16* ph = sm + KH_(st) + col * ALDK + ks * 16 + tig * 2;
                const __nv_bfloat16* pl = sm + KL_(st) + col * ALDK + ks * 16 + tig * 2;
                unsigned bh0 = lds32(ph), bh1 = lds32(ph + 8);
                unsigned bl0 = lds32(pl), bl1 = lds32(pl + 8);
                mma_bf16(S[nt], ah[0], ah[1], ah[2], ah[3], bh0, bh1);
                mma_bf16(S[nt], ah[0], ah[1], ah[2], ah[3], bl0, bl1);
                mma_bf16(S[nt], al[0], al[1], al[2], al[3], bh0, bh1);
            }
        }

        const bool needmask = (t >= 2 * qb);
        #pragma unroll
        for (int hh = 0; hh < 2; hh++) {
            const int gi = qi0 + w * 16 + hh * 8 + g;
            if (needmask) {
                #pragma unroll
                for (int nt = 0; nt < 8; nt++) {
                    #pragma unroll
                    for (int e = 0; e < 2; e++) {
                        int j = t * 64 + nt * 8 + tig * 2 + e;
                        if (j > gi) S[nt][hh * 2 + e] = -1e30f;
                    }
                }
            }
            float rs = 0.f;
            #pragma unroll
            for (int nt = 0; nt < 8; nt++) {
                float p0 = __expf(S[nt][hh * 2]);
                float p1 = __expf(S[nt][hh * 2 + 1]);
                S[nt][hh * 2]     = p0;
                S[nt][hh * 2 + 1] = p1;
                rs += p0 + p1;
            }
            l_[hh] += rs;
        }

        #pragma unroll
        for (int ks = 0; ks < 4; ks++) {
            unsigned ph[4], pl[4];
            split2(S[2 * ks][0],     S[2 * ks][1],     ph[0], pl[0]);
            split2(S[2 * ks][2],     S[2 * ks][3],     ph[1], pl[1]);
            split2(S[2 * ks + 1][0], S[2 * ks + 1][1], ph[2], pl[2]);
            split2(S[2 * ks + 1][2], S[2 * ks + 1][3], ph[3], pl[3]);
            #pragma unroll
            for (int nt = 0; nt < 8; nt++) {
                int dc = nt * 8 + g;
                const __nv_bfloat16* pvh = sm + VH_(st) + dc * ALDK + ks * 16 + tig * 2;
                const __nv_bfloat16* pvl = sm + VL_(st) + dc * ALDK + ks * 16 + tig * 2;
                unsigned bh0 = lds32(pvh), bh1 = lds32(pvh + 8);
                unsigned bl0 = lds32(pvl), bl1 = lds32(pvl + 8);
                mma_bf16(O[nt], ph[0], ph[1], ph[2], ph[3], bh0, bh1);
                mma_bf16(O[nt], ph[0], ph[1], ph[2], ph[3], bl0, bl1);
                mma_bf16(O[nt], pl[0], pl[1], pl[2], pl[3], bh0, bh1);
            }
        }
    }

    // epilogue: quad-reduce l, normalize, QUANTIZE to int8 dual-level
    #pragma unroll
    for (int hh = 0; hh < 2; hh++) {
        float lt = l_[hh];
        lt += __shfl_xor_sync(0xffffffffu, lt, 1);
        lt += __shfl_xor_sync(0xffffffffu, lt, 2);
        const float inv = 1.f / lt;
        const int gi = qi0 + w * 16 + hh * 8 + g;
        size_t orow = ((size_t)(b * N_SEQ + gi)) * DIM + head * DH;
        #pragma unroll
        for (int nt = 0; nt < 8; nt++) {
            int h0, l0, h1, l1;
            quant8(O[nt][hh * 2] * inv,     QS_ATT, h0, l0);
            quant8(O[nt][hh * 2 + 1] * inv, QS_ATT, h1, l1);
            size_t off = orow + nt * 8 + tig * 2;
            *(char2*)(a8h + off) = make_char2((signed char)h0, (signed char)h1);
            *(char2*)(a8l + off) = make_char2((signed char)l0, (signed char)l1);
        }
    }
}

// ---------------------------------------------------------------------------
extern "C" void kernel_launch(void* const* d_in, const int* in_sizes, int n_in,
                              void* d_out, int out_size) {
    const float* x      = (const float*)d_in[0];
    const float* Wq     = (const float*)d_in[1];
    const float* Wkv    = (const float*)d_in[2];
    const float* nullkv = (const float*)d_in[3];
    const float* Wout   = (const float*)d_in[4];
    float* out = (float*)d_out;

    __nv_bfloat16 *ahi, *alo, *wqh, *wql, *wkh, *wkl;
    __nv_bfloat16 *qhi, *qlo, *kh, *kl, *vth, *vtl;
    signed char *a8h, *a8l, *w8h, *w8l;
    cudaGetSymbolAddress((void**)&ahi,  g_ahi);
    cudaGetSymbolAddress((void**)&alo,  g_alo);
    cudaGetSymbolAddress((void**)&wqh,  g_wqh);
    cudaGetSymbolAddress((void**)&wql,  g_wql);
    cudaGetSymbolAddress((void**)&wkh,  g_wkh);
    cudaGetSymbolAddress((void**)&wkl,  g_wkl);
    cudaGetSymbolAddress((void**)&qhi,  g_qhi);
    cudaGetSymbolAddress((void**)&qlo,  g_qlo);
    cudaGetSymbolAddress((void**)&kh,   g_kh);
    cudaGetSymbolAddress((void**)&kl,   g_kl);
    cudaGetSymbolAddress((void**)&vth,  g_vth);
    cudaGetSymbolAddress((void**)&vtl,  g_vtl);
    cudaGetSymbolAddress((void**)&a8h,  g_a8h);
    cudaGetSymbolAddress((void**)&a8l,  g_a8l);
    cudaGetSymbolAddress((void**)&w8h,  g_w8h);
    cudaGetSymbolAddress((void**)&w8l,  g_w8l);

    cudaFuncSetAttribute(attn_mma_kernel,
                         cudaFuncAttributeMaxDynamicSharedMemorySize, ATT_SMEM);

    const int NEL = MTOT * DIM;     // 8M

    split_kernel<<<NEL / 4 / 256, 256>>>(x, ahi, alo, NEL);
    tsplit_kernel<<<dim3(32, 32), dim3(32, 8)>>>(Wq, DIM, wqh, wql);
    tsplit_kernel<<<dim3(2, 32),  dim3(32, 8)>>>(Wkv, DH, wkh, wkl);
    // Q = x @ Wq  (scale 0.125 + split + scatter to [b,h,n,d] hi/lo)
    gemm_mma_kernel<<<dim3(8, 64), 256>>>(ahi, alo, wqh, wql,
                                          nullptr, qhi, qlo, 1);
    // KV = x @ Wkv (split epilogue -> kh/kl + transposed vth/vtl)
    kvgemm_mma_kernel<<<64, 256>>>(ahi, alo, wkh, wkl, kh, kl, vth, vtl);
    // Wout -> transposed int8 dual-level
    tquant_kernel<<<dim3(32, 32), dim3(32, 8)>>>(Wout, w8h, w8l);
    // flash attention (emits int8 dual-level att directly)
    attn_mma_kernel<<<dim3(16, NB * NH), 256, ATT_SMEM>>>(
        qhi, qlo, kh, kl, vth, vtl, nullkv, a8h, a8l);
    // out = att @ Wout via int8 IMMA, 4 exact segments
    gemm_i8_kernel<<<dim3(8, 64), 256>>>(a8h, a8l, w8h, w8l, out);
}

// round 16
// speedup vs baseline: 1.3959x; 1.3959x over previous
#include <cuda_runtime.h>
#include <cuda_bf16.h>

#define N_SEQ 2048
#define DIM   1024
#define NB    4
#define NH    16
#define DH    64
#define MTOT (NB * N_SEQ)   // 8192

// ---------------------------------------------------------------------------
// Scratch (no allocs allowed -> __device__ globals)
// ---------------------------------------------------------------------------
__device__ __nv_bfloat16 g_ahi[(size_t)MTOT * DIM];     // x-split, later att-split
__device__ __nv_bfloat16 g_alo[(size_t)MTOT * DIM];
__device__ __nv_bfloat16 g_wqh[(size_t)DIM * DIM];      // Wq^T hi  [n][k]
__device__ __nv_bfloat16 g_wql[(size_t)DIM * DIM];
__device__ __nv_bfloat16 g_woh[(size_t)DIM * DIM];      // Wout^T hi
__device__ __nv_bfloat16 g_wol[(size_t)DIM * DIM];
__device__ __nv_bfloat16 g_wkh[(size_t)DH * DIM];       // Wkv^T hi [64][1024]
__device__ __nv_bfloat16 g_wkl[(size_t)DH * DIM];
__device__ __nv_bfloat16 g_qhi[(size_t)NB * NH * N_SEQ * DH];  // [b,h,n,d]
__device__ __nv_bfloat16 g_qlo[(size_t)NB * NH * N_SEQ * DH];
__device__ __nv_bfloat16 g_kh[(size_t)NB * N_SEQ * DH]; // token-indexed [b][n][d]
__device__ __nv_bfloat16 g_kl[(size_t)NB * N_SEQ * DH];
__device__ __nv_bfloat16 g_vth[(size_t)NB * DH * N_SEQ];// transposed [b][d][n]
__device__ __nv_bfloat16 g_vtl[(size_t)NB * DH * N_SEQ];

// ---------------------------------------------------------------------------
// helpers
// ---------------------------------------------------------------------------
__device__ __forceinline__ unsigned smem_u32(const void* p) {
    unsigned a;
    asm("{ .reg .u64 t; cvta.to.shared.u64 t, %1; cvt.u32.u64 %0, t; }"
        : "=r"(a) : "l"(p));
    return a;
}
__device__ __forceinline__ void cp16(unsigned dst, const void* src) {
    asm volatile("cp.async.cg.shared.global [%0], [%1], 16;"
                 :: "r"(dst), "l"(src) : "memory");
}
__device__ __forceinline__ void cp_commit() {
    asm volatile("cp.async.commit_group;" ::: "memory");
}
__device__ __forceinline__ void mma_bf16(float* acc, unsigned a0, unsigned a1,
                                         unsigned a2, unsigned a3,
                                         unsigned b0, unsigned b1) {
    asm volatile("mma.sync.aligned.m16n8k16.row.col.f32.bf16.bf16.f32 "
                 "{%0,%1,%2,%3}, {%4,%5,%6,%7}, {%8,%9}, {%0,%1,%2,%3};"
                 : "+f"(acc[0]), "+f"(acc[1]), "+f"(acc[2]), "+f"(acc[3])
                 : "r"(a0), "r"(a1), "r"(a2), "r"(a3), "r"(b0), "r"(b1));
}
__device__ __forceinline__ unsigned lds32(const __nv_bfloat16* p) {
    return *(const unsigned*)p;
}
__device__ __forceinline__ void split2(float x, float y, unsigned& hi, unsigned& lo) {
    __nv_bfloat16 hx = __float2bfloat16(x), hy = __float2bfloat16(y);
    __nv_bfloat162 h2 = __halves2bfloat162(hx, hy);
    hi = *(unsigned*)&h2;
    __nv_bfloat16 lx = __float2bfloat16(x - __bfloat162float(hx));
    __nv_bfloat16 ly = __float2bfloat16(y - __bfloat162float(hy));
    __nv_bfloat162 l2 = __halves2bfloat162(lx, ly);
    lo = *(unsigned*)&l2;
}
__device__ __forceinline__ void split1(float x, __nv_bfloat16& h, __nv_bfloat16& l) {
    h = __float2bfloat16(x);
    l = __float2bfloat16(x - __bfloat162float(h));
}
// tail-aware wait: keep at most 2 groups in flight (chunk c guaranteed done)
__device__ __forceinline__ void wait_tail(int c, int last) {
    if (c <= last - 2)      asm volatile("cp.async.wait_group 2;" ::: "memory");
    else if (c == last - 1) asm volatile("cp.async.wait_group 1;" ::: "memory");
    else                    asm volatile("cp.async.wait_group 0;" ::: "memory");
}

// ---------------------------------------------------------------------------
// split: fp32 -> bf16 hi + bf16 residual (linear)
// ---------------------------------------------------------------------------
__global__ void split_kernel(const float* __restrict__ s,
                             __nv_bfloat16* __restrict__ hi,
                             __nv_bfloat16* __restrict__ lo, int n) {
    int i = (blockIdx.x * blockDim.x + threadIdx.x) * 4;
    if (i >= n) return;
    float4 v = *(const float4*)(s + i);
    unsigned h0, l0, h1, l1;
    split2(v.x, v.y, h0, l0);
    split2(v.z, v.w, h1, l1);
    *(unsigned*)(hi + i)     = h0;
    *(unsigned*)(hi + i + 2) = h1;
    *(unsigned*)(lo + i)     = l0;
    *(unsigned*)(lo + i + 2) = l1;
}

// ---------------------------------------------------------------------------
// transpose+split weights: W[k][ncols] fp32 -> Wt hi/lo [ncols][1024] bf16
// ---------------------------------------------------------------------------
__global__ void tsplit_kernel(const float* __restrict__ W, int ncols,
                              __nv_bfloat16* __restrict__ hi,
                              __nv_bfloat16* __restrict__ lo) {
    __shared__ float t[32][33];
    int n0 = blockIdx.x * 32, k0 = blockIdx.y * 32;
    int tx = threadIdx.x, ty = threadIdx.y;
    #pragma unroll
    for (int j = 0; j < 32; j += 8)
        t[ty + j][tx] = W[(size_t)(k0 + ty + j) * ncols + n0 + tx];
    __syncthreads();
    #pragma unroll
    for (int j = 0; j < 32; j += 8) {
        float v = t[tx][ty + j];
        __nv_bfloat16 h, l;
        split1(v, h, l);
        size_t o = (size_t)(n0 + ty + j) * DIM + k0 + tx;
        hi[o] = h;
        lo[o] = l;
    }
}

// ---------------------------------------------------------------------------
// mma.sync split-bf16 GEMM: C[8192,1024] = A @ Bt^T, 3-term split.
// 4-stage cp.async ring (2 chunk-loads always in flight), ONE barrier per
// chunk (ring distance 3 between write stage and oldest live compute stage).
// mode 0: fp32 C;  mode 1: *0.125, split, scatter hi/lo to [b,h,n,d]
// ---------------------------------------------------------------------------
#define GLDK 40
#define GSTAGE_B (2 * 128 * GLDK * 2)      // bytes per stage (A then B)
#define GEMM_SMEM (4 * GSTAGE_B)           // 81920
__global__ __launch_bounds__(256)
void gemm_mma_kernel(const __nv_bfloat16* __restrict__ Ahi,
                     const __nv_bfloat16* __restrict__ Alo,
                     const __nv_bfloat16* __restrict__ Bhi,
                     const __nv_bfloat16* __restrict__ Blo,
                     float* __restrict__ C,
                     __nv_bfloat16* __restrict__ Chi,
                     __nv_bfloat16* __restrict__ Clo, int mode) {
    extern __shared__ __align__(16) char gsm[];
    const unsigned sbase = smem_u32(gsm);

    const int tid = threadIdx.x;
    const int lane = tid & 31;
    const int wid = tid >> 5;
    const int warpM = wid & 1;
    const int warpN = wid >> 1;
    const int g = lane >> 2, tig = lane & 3;
    const int m0 = blockIdx.y * 128;
    const int n0 = blockIdx.x * 128;

    float acc[4][4][4];
    #pragma unroll
    for (int i = 0; i < 4; i++)
        #pragma unroll
        for (int j = 0; j < 4; j++)
            #pragma unroll
            for (int e = 0; e < 4; e++) acc[i][j][e] = 0.f;

    const __nv_bfloat16* Aseg[3] = {Ahi, Ahi, Alo};
    const __nv_bfloat16* Bseg[3] = {Bhi, Blo, Bhi};

    const int lrow = tid >> 1;
    const int ljb  = (tid & 1) * 2;

    auto load_chunk = [&](int c, int st) {
        const int seg = c >> 5;
        const int k0  = (c & 31) * 32;
        const __nv_bfloat16* A = Aseg[seg];
        const __nv_bfloat16* B = Bseg[seg];
        const unsigned ab = sbase + st * GSTAGE_B;
        const unsigned bb = ab + 128 * GLDK * 2;
        #pragma unroll
        for (int i = 0; i < 2; i++) {
            int j = ljb + i;
            cp16(ab + (lrow * GLDK + j * 8) * 2,
                 A + (size_t)(m0 + lrow) * DIM + k0 + j * 8);
            cp16(bb + (lrow * GLDK + j * 8) * 2,
                 B + (size_t)(n0 + lrow) * DIM + k0 + j * 8);
        }
        cp_commit();
    };

    load_chunk(0, 0);
    load_chunk(1, 1);
    load_chunk(2, 2);

    #pragma unroll 1
    for (int c = 0; c < 96; c++) {
        const int st = c & 3;
        wait_tail(c, 95);
        __syncthreads();
        if (c + 3 < 96) load_chunk(c + 3, (c + 3) & 3);

        const __nv_bfloat16* pa = (const __nv_bfloat16*)(gsm + st * GSTAGE_B);
        const __nv_bfloat16* pb = pa + 128 * GLDK;
        #pragma unroll
        for (int ks = 0; ks < 2; ks++) {
            unsigned a[4][4];
            #pragma unroll
            for (int mt = 0; mt < 4; mt++) {
                int row = warpM * 64 + mt * 16 + g;
                const __nv_bfloat16* p = pa + row * GLDK + ks * 16 + tig * 2;
                a[mt][0] = lds32(p);
                a[mt][1] = lds32(p + 8 * GLDK);
                a[mt][2] = lds32(p + 8);
                a[mt][3] = lds32(p + 8 * GLDK + 8);
            }
            #pragma unroll
            for (int nt = 0; nt < 4; nt++) {
                int col = warpN * 32 + nt * 8 + g;
                const __nv_bfloat16* p = pb + col * GLDK + ks * 16 + tig * 2;
                unsigned b0 = lds32(p), b1 = lds32(p + 8);
                #pragma unroll
                for (int mt = 0; mt < 4; mt++)
                    mma_bf16(acc[mt][nt], a[mt][0], a[mt][1], a[mt][2], a[mt][3], b0, b1);
            }
        }
    }

    #pragma unroll
    for (int mt = 0; mt < 4; mt++) {
        #pragma unroll
        for (int nt = 0; nt < 4; nt++) {
            int gr = m0 + warpM * 64 + mt * 16 + g;
            int gc = n0 + warpN * 32 + nt * 8 + tig * 2;
            #pragma unroll
            for (int hh = 0; hh < 2; hh++) {
                int r = gr + hh * 8;
                if (mode == 1) {
                    float vx = acc[mt][nt][hh * 2] * 0.125f;
                    float vy = acc[mt][nt][hh * 2 + 1] * 0.125f;
                    unsigned h, l;
                    split2(vx, vy, h, l);
                    int b = r >> 11, ii = r & 2047, hd = gc >> 6;
                    size_t off = (((size_t)(b * NH + hd) * N_SEQ + ii)) * DH + (gc & 63);
                    *(unsigned*)(Chi + off) = h;
                    *(unsigned*)(Clo + off) = l;
                } else {
                    float2 v = make_float2(acc[mt][nt][hh * 2], acc[mt][nt][hh * 2 + 1]);
                    *(float2*)(C + (size_t)r * DIM + gc) = v;
                }
            }
        }
    }
}

// ---------------------------------------------------------------------------
// KV projection, same 4-stage ring. kv = x @ Wkv, tile 128x64, K=3x1024.
// Epilogue writes K hi/lo [b][n][64] and transposed V hi/lo [b][64][n].
// ---------------------------------------------------------------------------
#define KSTAGE_B ((128 * GLDK + 64 * GLDK) * 2)    // 15360
#define KV_SMEM (4 * KSTAGE_B)                     // 61440
__global__ __launch_bounds__(256)
void kvgemm_mma_kernel(const __nv_bfloat16* __restrict__ Ahi,
                       const __nv_bfloat16* __restrict__ Alo,
                       const __nv_bfloat16* __restrict__ Bhi,
                       const __nv_bfloat16* __restrict__ Blo,
                       __nv_bfloat16* __restrict__ kh,
                       __nv_bfloat16* __restrict__ kl,
                       __nv_bfloat16* __restrict__ vth,
                       __nv_bfloat16* __restrict__ vtl) {
    extern __shared__ __align__(16) char gsm[];
    const unsigned sbase = smem_u32(gsm);

    const int tid = threadIdx.x;
    const int lane = tid & 31;
    const int w = tid >> 5;            // 8 warps, warp w: rows w*16..w*16+15
    const int g = lane >> 2, tig = lane & 3;
    const int m0 = blockIdx.x * 128;

    float acc[8][4];
    #pragma unroll
    for (int i = 0; i < 8; i++)
        #pragma unroll
        for (int e = 0; e < 4; e++) acc[i][e] = 0.f;

    const __nv_bfloat16* Aseg[3] = {Ahi, Ahi, Alo};
    const __nv_bfloat16* Bseg[3] = {Bhi, Blo, Bhi};

    auto load_chunk = [&](int c, int st) {
        const int seg = c >> 5;
        const int k0  = (c & 31) * 32;
        const __nv_bfloat16* A = Aseg[seg];
        const __nv_bfloat16* B = Bseg[seg];
        const unsigned ab = sbase + st * KSTAGE_B;
        const unsigned bb = ab + 128 * GLDK * 2;
        {   // A: 128 rows x 32k; 2 cp16/thread
            const int row = tid >> 1;
            const int jb  = (tid & 1) * 2;
            #pragma unroll
            for (int i = 0; i < 2; i++) {
                int j = jb + i;
                cp16(ab + (row * GLDK + j * 8) * 2,
                     A + (size_t)(m0 + row) * DIM + k0 + j * 8);
            }
        }
        {   // B: 64 rows x 32k; 1 cp16/thread
            const int row = tid >> 2;
            const int j   = tid & 3;
            cp16(bb + (row * GLDK + j * 8) * 2,
                 B + (size_t)row * DIM + k0 + j * 8);
        }
        cp_commit();
    };

    load_chunk(0, 0);
    load_chunk(1, 1);
    load_chunk(2, 2);

    #pragma unroll 1
    for (int c = 0; c < 96; c++) {
        const int st = c & 3;
        wait_tail(c, 95);
        __syncthreads();
        if (c + 3 < 96) load_chunk(c + 3, (c + 3) & 3);

        const __nv_bfloat16* pa = (const __nv_bfloat16*)(gsm + st * KSTAGE_B);
        const __nv_bfloat16* pb = pa + 128 * GLDK;
        #pragma unroll
        for (int ks = 0; ks < 2; ks++) {
            unsigned a[4];
            {
                int row = w * 16 + g;
                const __nv_bfloat16* p = pa + row * GLDK + ks * 16 + tig * 2;
                a[0] = lds32(p);
                a[1] = lds32(p + 8 * GLDK);
                a[2] = lds32(p + 8);
                a[3] = lds32(p + 8 * GLDK + 8);
            }
            #pragma unroll
            for (int nt = 0; nt < 8; nt++) {
                int col = nt * 8 + g;
                const __nv_bfloat16* p = pb + col * GLDK + ks * 16 + tig * 2;
                unsigned b0 = lds32(p), b1 = lds32(p + 8);
                mma_bf16(acc[nt], a[0], a[1], a[2], a[3], b0, b1);
            }
        }
    }

    #pragma unroll
    for (int nt = 0; nt < 8; nt++) {
        #pragma unroll
        for (int hh = 0; hh < 2; hh++) {
            int gr = m0 + w * 16 + hh * 8 + g;          // global token row
            int b = gr >> 11, ii = gr & 2047;
            int cc = nt * 8 + tig * 2;
            float vx = acc[nt][hh * 2], vy = acc[nt][hh * 2 + 1];
            unsigned h, l;
            split2(vx, vy, h, l);
            size_t ko = ((size_t)b * N_SEQ + ii) * DH + cc;
            *(unsigned*)(kh + ko) = h;
            *(unsigned*)(kl + ko) = l;
            __nv_bfloat16 h0, l0, h1, l1;
            split1(vx, h0, l0);
            split1(vy, h1, l1);
            size_t vo = ((size_t)b * DH + cc) * N_SEQ + ii;
            vth[vo] = h0; vtl[vo] = l0;
            vth[vo + N_SEQ] = h1; vtl[vo + N_SEQ] = l1;
        }
    }
}

// ---------------------------------------------------------------------------
// Flash attention on mma.sync, split-bf16 (3-term), double-buffered K/V,
// no-max softmax (scores O(1)-bounded). Unchanged from the R13 passing base.
// ---------------------------------------------------------------------------
#define ALDK 72
#define QH0  0
#define QL0  (128 * ALDK)
#define KVB  (2 * 128 * ALDK)
#define KVST (4 * 64 * ALDK)
#define KH_(s) (KVB + (s) * KVST)
#define KL_(s) (KH_(s) + 64 * ALDK)
#define VH_(s) (KH_(s) + 2 * 64 * ALDK)
#define VL_(s) (KH_(s) + 3 * 64 * ALDK)
#define ATT_SMEM ((KVB + 2 * KVST) * 2)   // 110592 bytes

__global__ __launch_bounds__(256)
void attn_mma_kernel(const __nv_bfloat16* __restrict__ qhi,
                     const __nv_bfloat16* __restrict__ qlo,
                     const __nv_bfloat16* __restrict__ kh,
                     const __nv_bfloat16* __restrict__ kl,
                     const __nv_bfloat16* __restrict__ vth,
                     const __nv_bfloat16* __restrict__ vtl,
                     const float* __restrict__ nullkv,
                     __nv_bfloat16* __restrict__ atthi,
                     __nv_bfloat16* __restrict__ attlo) {
    extern __shared__ __align__(16) __nv_bfloat16 sm[];
    const unsigned sb = smem_u32(sm);

    const int tid = threadIdx.x;
    const int w = tid >> 5;
    const int lane = tid & 31;
    const int g = lane >> 2, tig = lane & 3;
    const int qb = 15 - blockIdx.x;                  // heavy blocks first
    const int bh = blockIdx.y;
    const int b = bh >> 4, head = bh & 15;
    const int qi0 = qb * 128;
    const int ntiles = 2 * qb + 2;

    auto load_kv = [&](int t, int st) {
        const int rr = tid >> 2, q = tid & 3;
        size_t ko = ((size_t)b * N_SEQ + t * 64 + rr) * DH;
        size_t vo = ((size_t)b * DH + rr) * N_SEQ + t * 64;
        #pragma unroll
        for (int i = 0; i < 2; i++) {
            int j = q * 2 + i;
            cp16(sb + (KH_(st) + rr * ALDK + j * 8) * 2, kh + ko + j * 8);
            cp16(sb + (KL_(st) + rr * ALDK + j * 8) * 2, kl + ko + j * 8);
            cp16(sb + (VH_(st) + rr * ALDK + j * 8) * 2, vth + vo + j * 8);
            cp16(sb + (VL_(st) + rr * ALDK + j * 8) * 2, vtl + vo + j * 8);
        }
        cp_commit();
    };

    {
        const int row = tid >> 1;
        const int half = tid & 1;
        size_t qo = ((size_t)bh * N_SEQ + qi0 + row) * DH + half * 32;
        #pragma unroll
        for (int j = 0; j < 4; j++) {
            cp16(sb + (QH0 + row * ALDK + half * 32 + j * 8) * 2, qhi + qo + j * 8);
            cp16(sb + (QL0 + row * ALDK + half * 32 + j * 8) * 2, qlo + qo + j * 8);
        }
    }
    load_kv(0, 0);

    float l_[2], O[8][4];

    #pragma unroll 1
    for (int t = 0; t < ntiles; t++) {
        const int st = t & 1;
        if (t) __syncthreads();
        if (t + 1 < ntiles) {
            load_kv(t + 1, st ^ 1);
            asm volatile("cp.async.wait_group 1;" ::: "memory");
        } else {
            asm volatile("cp.async.wait_group 0;" ::: "memory");
        }
        __syncthreads();

        if (t == 0) {
            float nk[16];
            #pragma unroll
            for (int d = 0; d < 16; d++) nk[d] = nullkv[tig * 16 + d];
            float e0s[2];
            #pragma unroll
            for (int hh = 0; hh < 2; hh++) {
                int row = w * 16 + hh * 8 + g;
                const __nv_bfloat16* ph = sm + QH0 + row * ALDK + tig * 16;
                const __nv_bfloat16* pl = sm + QL0 + row * ALDK + tig * 16;
                float s = 0.f;
                #pragma unroll
                for (int d = 0; d < 16; d++)
                    s = fmaf(__bfloat162float(ph[d]) + __bfloat162float(pl[d]),
                             nk[d], s);
                s += __shfl_xor_sync(0xffffffffu, s, 1);
                s += __shfl_xor_sync(0xffffffffu, s, 2);
                e0s[hh] = __expf(s);
                l_[hh] = (tig == 0) ? e0s[hh] : 0.f;
            }
            #pragma unroll
            for (int nt = 0; nt < 8; nt++) {
                float v0 = nullkv[nt * 8 + tig * 2];
                float v1 = nullkv[nt * 8 + tig * 2 + 1];
                O[nt][0] = v0 * e0s[0]; O[nt][1] = v1 * e0s[0];
                O[nt][2] = v0 * e0s[1]; O[nt][3] = v1 * e0s[1];
            }
        }

        float S[8][4];
        #pragma unroll
        for (int nt = 0; nt < 8; nt++)
            #pragma unroll
            for (int e = 0; e < 4; e++) S[nt][e] = 0.f;

        #pragma unroll
        for (int ks = 0; ks < 4; ks++) {
            unsigned ah[4], al[4];
            {
                int row = w * 16 + g;
                const __nv_bfloat16* ph = sm + QH0 + row * ALDK + ks * 16 + tig * 2;
                const __nv_bfloat16* pl = sm + QL0 + row * ALDK + ks * 16 + tig * 2;
                ah[0] = lds32(ph);            ah[1] = lds32(ph + 8 * ALDK);
                ah[2] = lds32(ph + 8);        ah[3] = lds32(ph + 8 * ALDK + 8);
                al[0] = lds32(pl);            al[1] = lds32(pl + 8 * ALDK);
                al[2] = lds32(pl + 8);        al[3] = lds32(pl + 8 * ALDK + 8);
            }
            #pragma unroll
            for (int nt = 0; nt < 8; nt++) {
                int col = nt * 8 + g;
                const __nv_bfloat16* ph = sm + KH_(st) + col * ALDK + ks * 16 + tig * 2;
                const __nv_bfloat16* pl = sm + KL_(st) + col * ALDK + ks * 16 + tig * 2;
                unsigned bh0 = lds32(ph), bh1 = lds32(ph + 8);
                unsigned bl0 = lds32(pl), bl1 = lds32(pl + 8);
                mma_bf16(S[nt], ah[0], ah[1], ah[2], ah[3], bh0, bh1);
                mma_bf16(S[nt], ah[0], ah[1], ah[2], ah[3], bl0, bl1);
                mma_bf16(S[nt], al[0], al[1], al[2], al[3], bh0, bh1);
            }
        }

        const bool needmask = (t >= 2 * qb);
        #pragma unroll
        for (int hh = 0; hh < 2; hh++) {
            const int gi = qi0 + w * 16 + hh * 8 + g;
            if (needmask) {
                #pragma unroll
                for (int nt = 0; nt < 8; nt++) {
                    #pragma unroll
                    for (int e = 0; e < 2; e++) {
                        int j = t * 64 + nt * 8 + tig * 2 + e;
                        if (j > gi) S[nt][hh * 2 + e] = -1e30f;
                    }
                }
            }
            float rs = 0.f;
            #pragma unroll
            for (int nt = 0; nt < 8; nt++) {
                float p0 = __expf(S[nt][hh * 2]);
                float p1 = __expf(S[nt][hh * 2 + 1]);
                S[nt][hh * 2]     = p0;
                S[nt][hh * 2 + 1] = p1;
                rs += p0 + p1;
            }
            l_[hh] += rs;
        }

        #pragma unroll
        for (int ks = 0; ks < 4; ks++) {
            unsigned ph[4], pl[4];
            split2(S[2 * ks][0],     S[2 * ks][1],     ph[0], pl[0]);
            split2(S[2 * ks][2],     S[2 * ks][3],     ph[1], pl[1]);
            split2(S[2 * ks + 1][0], S[2 * ks + 1][1], ph[2], pl[2]);
            split2(S[2 * ks + 1][2], S[2 * ks + 1][3], ph[3], pl[3]);
            #pragma unroll
            for (int nt = 0; nt < 8; nt++) {
                int dc = nt * 8 + g;
                const __nv_bfloat16* pvh = sm + VH_(st) + dc * ALDK + ks * 16 + tig * 2;
                const __nv_bfloat16* pvl = sm + VL_(st) + dc * ALDK + ks * 16 + tig * 2;
                unsigned bh0 = lds32(pvh), bh1 = lds32(pvh + 8);
                unsigned bl0 = lds32(pvl), bl1 = lds32(pvl + 8);
                mma_bf16(O[nt], ph[0], ph[1], ph[2], ph[3], bh0, bh1);
                mma_bf16(O[nt], ph[0], ph[1], ph[2], ph[3], bl0, bl1);
                mma_bf16(O[nt], pl[0], pl[1], pl[2], pl[3], bh0, bh1);
            }
        }
    }

    #pragma unroll
    for (int hh = 0; hh < 2; hh++) {
        float lt = l_[hh];
        lt += __shfl_xor_sync(0xffffffffu, lt, 1);
        lt += __shfl_xor_sync(0xffffffffu, lt, 2);
        const float inv = 1.f / lt;
        const int gi = qi0 + w * 16 + hh * 8 + g;
        size_t orow = ((size_t)(b * N_SEQ + gi)) * DIM + head * DH;
        #pragma unroll
        for (int nt = 0; nt < 8; nt++) {
            unsigned h, l;
            split2(O[nt][hh * 2] * inv, O[nt][hh * 2 + 1] * inv, h, l);
            size_t off = orow + nt * 8 + tig * 2;
            *(unsigned*)(atthi + off) = h;
            *(unsigned*)(attlo + off) = l;
        }
    }
}

// ---------------------------------------------------------------------------
extern "C" void kernel_launch(void* const* d_in, const int* in_sizes, int n_in,
                              void* d_out, int out_size) {
    const float* x      = (const float*)d_in[0];
    const float* Wq     = (const float*)d_in[1];
    const float* Wkv    = (const float*)d_in[2];
    const float* nullkv = (const float*)d_in[3];
    const float* Wout   = (const float*)d_in[4];
    float* out = (float*)d_out;

    __nv_bfloat16 *ahi, *alo, *wqh, *wql, *woh, *wol, *wkh, *wkl;
    __nv_bfloat16 *qhi, *qlo, *kh, *kl, *vth, *vtl;
    cudaGetSymbolAddress((void**)&ahi,  g_ahi);
    cudaGetSymbolAddress((void**)&alo,  g_alo);
    cudaGetSymbolAddress((void**)&wqh,  g_wqh);
    cudaGetSymbolAddress((void**)&wql,  g_wql);
    cudaGetSymbolAddress((void**)&woh,  g_woh);
    cudaGetSymbolAddress((void**)&wol,  g_wol);
    cudaGetSymbolAddress((void**)&wkh,  g_wkh);
    cudaGetSymbolAddress((void**)&wkl,  g_wkl);
    cudaGetSymbolAddress((void**)&qhi,  g_qhi);
    cudaGetSymbolAddress((void**)&qlo,  g_qlo);
    cudaGetSymbolAddress((void**)&kh,   g_kh);
    cudaGetSymbolAddress((void**)&kl,   g_kl);
    cudaGetSymbolAddress((void**)&vth,  g_vth);
    cudaGetSymbolAddress((void**)&vtl,  g_vtl);

    cudaFuncSetAttribute(attn_mma_kernel,
                         cudaFuncAttributeMaxDynamicSharedMemorySize, ATT_SMEM);
    cudaFuncSetAttribute(gemm_mma_kernel,
                         cudaFuncAttributeMaxDynamicSharedMemorySize, GEMM_SMEM);
    cudaFuncSetAttribute(kvgemm_mma_kernel,
                         cudaFuncAttributeMaxDynamicSharedMemorySize, KV_SMEM);

    const int NEL = MTOT * DIM;     // 8M

    // (gemm_mma in the 4th launch slot -> lands in the ncu capture window)
    split_kernel<<<NEL / 4 / 256, 256>>>(x, ahi, alo, NEL);
    tsplit_kernel<<<dim3(32, 32), dim3(32, 8)>>>(Wq, DIM, wqh, wql);
    tsplit_kernel<<<dim3(2, 32),  dim3(32, 8)>>>(Wkv, DH, wkh, wkl);
    // Q = x @ Wq  (scale 0.125 + split + scatter to [b,h,n,d] hi/lo)
    gemm_mma_kernel<<<dim3(8, 64), 256, GEMM_SMEM>>>(ahi, alo, wqh, wql,
                                                     nullptr, qhi, qlo, 1);
    // KV = x @ Wkv (split epilogue -> kh/kl + transposed vth/vtl)
    kvgemm_mma_kernel<<<64, 256, KV_SMEM>>>(ahi, alo, wkh, wkl, kh, kl, vth, vtl);
    // Wout -> transposed bf16 hi/lo
    tsplit_kernel<<<dim3(32, 32), dim3(32, 8)>>>(Wout, DIM, woh, wol);
    // flash attention (no-max softmax; writes pre-split att into ahi/alo)
    attn_mma_kernel<<<dim3(16, NB * NH), 256, ATT_SMEM>>>(
        qhi, qlo, kh, kl, vth, vtl, nullkv, ahi, alo);
    // out = att @ Wout
    gemm_mma_kernel<<<dim3(8, 64), 256, GEMM_SMEM>>>(ahi, alo, woh, wol,
                                                     out, nullptr, nullptr, 0);
}